// round 16
// baseline (speedup 1.0000x reference)
#include <cuda_runtime.h>
#include <math.h>

#define R_HASH 0.2f
#define EPSF   1e-12f
#define BATCH  4096

// scratch (device globals: sanctioned scratch mechanism)
__device__ float g_h1[BATCH * 16 * 16 * 16];
__device__ float g_h2[BATCH * 20 * 8 * 8];
__device__ int   g_qh[3 * BATCH];
__device__ int   g_kh[96];
__device__ float g_aux[48];
__device__ __align__(16) float g_w1p[48 * 28];   // padded weights, stride 28
__device__ __align__(16) float g_w2p[320 * 28];
__device__ __align__(16) float g_w3p[400 * 28];

// ---------------------------------------------------------------------------
// Fused setup kernel: blocks 0-2 = filter hashes (one warp per filter,
// lane-parallel dot products); blocks 3-7 = weight padding + aux sums.
// ---------------------------------------------------------------------------
__global__ void kh_all(const float* __restrict__ W1, const float* __restrict__ a1,
                       const float* __restrict__ c1,
                       const float* __restrict__ W2, const float* __restrict__ a2,
                       const float* __restrict__ c2,
                       const float* __restrict__ W3, const float* __restrict__ a3,
                       const float* __restrict__ c3)
{
    const int blk = blockIdx.x;
    if (blk < 3) {
        const float* W = (blk == 0) ? W1 : (blk == 1) ? W2 : W3;
        const float* a = (blk == 0) ? a1 : (blk == 1) ? a2 : a3;
        const float* c = (blk == 0) ? c1 : (blk == 1) ? c2 : c3;
        const int Cout = (blk == 0) ? 16 : 20;
        const int d    = (blk == 0) ? 75 : (blk == 1) ? 400 : 500;
        int* khp = g_kh + blk * 32;

        __shared__ float norms[32];
        __shared__ float smx;
        int w = threadIdx.x >> 5, lane = threadIdx.x & 31;

        for (int f = w; f < Cout; f += 8) {
            float s = 0.f;
            for (int j = lane; j < d; j += 32) { float v = W[f * d + j]; s += v * v; }
            #pragma unroll
            for (int off = 16; off; off >>= 1)
                s += __shfl_xor_sync(0xffffffffu, s, off);
            if (lane == 0) norms[f] = sqrtf(s);
        }
        __syncthreads();
        if (threadIdx.x < 32) {
            float v = (lane < Cout) ? norms[lane] : 0.f;
            #pragma unroll
            for (int off = 16; off; off >>= 1)
                v = fmaxf(v, __shfl_xor_sync(0xffffffffu, v, off));
            if (lane == 0) smx = v;
        }
        __syncthreads();
        const float scale = 1.f / (smx + EPSF);
        for (int f = w; f < Cout; f += 8) {
            float dot = 0.f, ss = 0.f;
            for (int j = lane; j < d; j += 32) {
                float v = W[f * d + j] * scale;
                dot += v * a[j];
                ss  += v * v;
            }
            #pragma unroll
            for (int off = 16; off; off >>= 1) {
                dot += __shfl_xor_sync(0xffffffffu, dot, off);
                ss  += __shfl_xor_sync(0xffffffffu, ss, off);
            }
            if (lane == 0) {
                float n = sqrtf(ss), p = n;
                #pragma unroll
                for (int m = 0; m < 5; m++) { p = p * p; dot += p * a[d + m]; }
                dot += c[0];
                long long fl = (long long)floorf(dot / R_HASH);
                khp[f] = (int)(((fl % 2) + 2) % 2);
            }
        }
    } else {
        const int t = threadIdx.x;
        if (blk == 3) {
            if (t < 16) {
                float s = 0.f; for (int j = 0; j < 25; j++) s += a2[t * 25 + j];
                g_aux[t] = s;
            } else if (t >= 32 && t < 52) {
                int r = t - 32;
                float s = 0.f; for (int j = 0; j < 25; j++) s += a3[r * 25 + j];
                g_aux[16 + r] = s;
            } else if (t >= 64 && t < 67) {
                int r = t - 64;
                float s = 0.f; for (int j = 0; j < 25; j++) s += a1[r * 25 + j];
                g_aux[38 + r] = s;
            } else if (t == 67) {
                float s = 0.f; for (int m = 0; m < 5; m++) s += a2[400 + m];
                g_aux[36] = s;
            } else if (t == 68) {
                float s = 0.f; for (int m = 0; m < 5; m++) s += a3[500 + m];
                g_aux[37] = s;
            } else if (t == 69) {
                float s = 0.f; for (int m = 0; m < 5; m++) s += a1[75 + m];
                g_aux[41] = s;
            }
        }
        const int base = (blk - 3) * 256 + t;
        const int stride = 5 * 256;
        for (int i = base; i < 48 * 28; i += stride) {
            int f = i / 28, k = i % 28;
            g_w1p[i] = (k < 25) ? W1[f * 25 + k] : 0.f;
        }
        for (int i = base; i < 320 * 28; i += stride) {
            int f = i / 28, k = i % 28;
            g_w2p[i] = (k < 25) ? W2[f * 25 + k] : 0.f;
        }
        for (int i = base; i < 400 * 28; i += stride) {
            int f = i / 28, k = i % 28;
            g_w3p[i] = (k < 25) ? W3[f * 25 + k] : 0.f;
        }
    }
}

// ---------------------------------------------------------------------------
// Fused conv5x5(pad2)+bias+relu+mask+maxpool2 (R15 structure).
// Staging: zero-fill tile (float4 STS), then interior rows via float4 LDG.
// NOPREV=true: n_ci==CIN. FCOUT=true: FC epilogue writes final [B,10].
// QHIN=true (requires NOPREV, SPB==1): compute own query hash from the staged
// tile (padding is zero so whole-tile sums == interior sums), write it to
// gmem for the next layer, and build the output-channel list in-block.
// ---------------------------------------------------------------------------
template <int CIN, int COUT, int H, int W, int WPAD, int SPB, int T, int MINB,
          bool EPI, bool NOPREV, bool FCOUT, bool QHIN>
__global__ __launch_bounds__(T, MINB)
void conv_fused(const float* __restrict__ in, float* __restrict__ out,
                const float* __restrict__ wpad, const float* __restrict__ bias,
                const int* __restrict__ kh, const int* __restrict__ qh,
                const int* __restrict__ kh_prev, const int* __restrict__ qh_prev,
                const float* __restrict__ asum_next,
                const float* __restrict__ tail_next,
                const float* __restrict__ c_next, int* __restrict__ qh_next,
                const float* __restrict__ Wo, const float* __restrict__ bo,
                float* __restrict__ fcout,
                const float* __restrict__ asum_own,
                const float* __restrict__ tail_own,
                const float* __restrict__ c_own, int* __restrict__ qh_own)
{
    constexpr int HP = H + 4;
    constexpr int PH = H / 2, PW = W / 2, PX2 = PW / 2;
    constexpr int PP = PH * PX2;
    constexpr int SEG = (PP < 32) ? PP : 32;
    constexpr int CHW = HP * WPAD;
    constexpr int WG = W / 4;                 // float4 groups per row
    constexpr int FCN = COUT * PH * PW;       // per-sample flattened size
    constexpr int NW = T / 32;

    extern __shared__ float sm[];
    float* sx  = sm;
    float* scm = sx + SPB * CIN * CHW;
    float* sh3 = scm + SPB * COUT;            // FCOUT: SPB*FCN, else 0
    int* nact  = (int*)(sh3 + (FCOUT ? SPB * FCN : 0));
    int* soff  = nact + SPB;
    int* actco = soff + SPB + 1;
    int* nci   = actco + SPB * COUT;
    int* actci = nci + SPB;
    int* sxoff = actci + SPB * CIN;
    float* csum = (float*)(sxoff + SPB + 1);  // QHIN: CIN*NW warp partials

    const int b0 = blockIdx.x * SPB;
    const int t  = threadIdx.x;

    if (!QHIN && t < SPB) {
        int s = t, n = 0, qv = qh[b0 + s];
        for (int co = 0; co < COUT; co++)
            if (kh[co] == qv) actco[s * COUT + n++] = co;
        nact[s] = n;
    } else if (t >= 32 && t < 32 + SPB) {
        int s = t - 32, n = 0;
        if (!NOPREV) {
            int qv = qh_prev[b0 + s];
            for (int c = 0; c < CIN; c++)
                if (kh_prev[c] == qv) actci[s * CIN + n++] = c;
        } else {
            for (int c = 0; c < CIN; c++) actci[s * CIN + n++] = c;
        }
        nci[s] = n;
    }
    if (EPI) for (int i = t; i < SPB * COUT; i += T) scm[i] = 0.f;
    if (FCOUT) for (int i = t; i < SPB * FCN; i += T) sh3[i] = 0.f;
    __syncthreads();
    if (t == 0) {
        int xo = 0;
        for (int s = 0; s < SPB; s++) {
            sxoff[s] = xo; xo += NOPREV ? CIN : nci[s];
        }
        sxoff[SPB] = xo;
        if (!QHIN) {
            int o = 0;
            for (int s = 0; s < SPB; s++) { soff[s] = o; o += nact[s] * PP; }
            soff[SPB] = o;
        }
    }
    __syncthreads();

    const int total_ch = sxoff[SPB];
    // zero-fill used portion of tile (float4 STS)
    {
        float4 z = make_float4(0.f, 0.f, 0.f, 0.f);
        float4* sx4 = (float4*)sx;
        const int n4 = total_ch * (CHW / 4);
        for (int i = t; i < n4; i += T) sx4[i] = z;
    }
    __syncthreads();
    // interior rows via float4 LDG + 4 scalar STS
    for (int i = t; i < total_ch * H * WG; i += T) {
        int xg = i % WG; int rest = i / WG;
        int y = rest % H; int ch = rest / H;
        int s = 0;
        #pragma unroll
        for (int ss = 0; ss < SPB - 1; ss++)
            if (ch >= sxoff[ss + 1]) s = ss + 1;
        int c = NOPREV ? (ch - sxoff[s]) : actci[s * CIN + (ch - sxoff[s])];
        float4 v = *(const float4*)(in + ((size_t)(b0 + s) * CIN + c) * (H * W)
                                    + y * W + 4 * xg);
        float* dst = sx + ch * CHW + (y + 2) * WPAD + 4 * xg + 2;
        dst[0] = v.x; dst[1] = v.y; dst[2] = v.z; dst[3] = v.w;
    }
    __syncthreads();

    if (QHIN) {
        // own query hash from staged tile (padding contributes exact zeros)
        int w = t >> 5, lane = t & 31;
        #pragma unroll
        for (int c = 0; c < CIN; c++) {
            float s = 0.f;
            for (int i = t; i < CHW; i += T) s += sx[c * CHW + i];
            #pragma unroll
            for (int off = 16; off; off >>= 1)
                s += __shfl_xor_sync(0xffffffffu, s, off);
            if (lane == 0) csum[c * NW + w] = s;
        }
        __syncthreads();
        if (t == 0) {
            float dot = 0.f, ss = 0.f;
            const float inv = 1.f / (float)(H * W);
            for (int c = 0; c < CIN; c++) {
                float s = 0.f;
                for (int i = 0; i < NW; i++) s += csum[c * NW + i];
                float cm = s * inv;
                dot += cm * asum_own[c];
                ss  += cm * cm;
            }
            float v = dot / (sqrtf(25.f * ss) + EPSF) + 0.5f * tail_own[0] + c_own[0];
            long long f = (long long)floorf(v / R_HASH);
            int qv = (int)(((f % 2) + 2) % 2);
            qh_own[b0] = qv;
            int n = 0;
            for (int co = 0; co < COUT; co++)
                if (kh[co] == qv) actco[n++] = co;
            nact[0] = n;
            soff[0] = 0; soff[1] = n * PP;
        }
        __syncthreads();
    }
    const int total = soff[SPB];

    for (int item = t;; item += T) {
        if (!__ballot_sync(0xffffffffu, item < total)) break;
        float val = 0.f;
        int s = 0, co = 0;
        if (item < total) {
            #pragma unroll
            for (int ss = 0; ss < SPB - 1; ss++)
                if (item >= soff[ss + 1]) s = ss + 1;
            int local = item - soff[s];
            co = actco[s * COUT + local / PP];
            int rr = local % PP;
            int py = rr / PX2, px2 = rr % PX2;

            float acc[2][4] = {};
            const float* xb = sx + (size_t)sxoff[s] * CHW + (2 * py) * WPAD + 4 * px2;
            const int n_ci = NOPREV ? CIN : nci[s];
            const int* ci = actci + s * CIN;
            const float* wb_ = wpad + (size_t)co * CIN * 28;

            for (int j = 0; j < n_ci; j++) {
                int c = NOPREV ? j : ci[j];
                const float4* wr = (const float4*)(wb_ + c * 28);
                float4 q0 = __ldg(wr + 0), q1 = __ldg(wr + 1), q2 = __ldg(wr + 2);
                float4 q3 = __ldg(wr + 3), q4 = __ldg(wr + 4), q5 = __ldg(wr + 5);
                float4 q6 = __ldg(wr + 6);
                float w[25] = {q0.x, q0.y, q0.z, q0.w, q1.x, q1.y, q1.z, q1.w,
                               q2.x, q2.y, q2.z, q2.w, q3.x, q3.y, q3.z, q3.w,
                               q4.x, q4.y, q4.z, q4.w, q5.x, q5.y, q5.z, q5.w,
                               q6.x};
                const float* xs = xb + j * CHW;
                #pragma unroll
                for (int rw = 0; rw < 6; rw++) {
                    float4 x0 = *(const float4*)(xs + rw * WPAD);
                    float4 x1 = *(const float4*)(xs + rw * WPAD + 4);
                    float xr[8] = {x0.x, x0.y, x0.z, x0.w, x1.x, x1.y, x1.z, x1.w};
                    if (rw < 5) {
                        #pragma unroll
                        for (int kx = 0; kx < 5; kx++) {
                            float wa = w[rw * 5 + kx];
                            acc[0][0] += xr[kx + 0] * wa;
                            acc[0][1] += xr[kx + 1] * wa;
                            acc[0][2] += xr[kx + 2] * wa;
                            acc[0][3] += xr[kx + 3] * wa;
                        }
                    }
                    if (rw > 0) {
                        #pragma unroll
                        for (int kx = 0; kx < 5; kx++) {
                            float wb = w[(rw - 1) * 5 + kx];
                            acc[1][0] += xr[kx + 0] * wb;
                            acc[1][1] += xr[kx + 1] * wb;
                            acc[1][2] += xr[kx + 2] * wb;
                            acc[1][3] += xr[kx + 3] * wb;
                        }
                    }
                }
            }
            float bv = __ldg(bias + co);
            float v00 = fmaxf(acc[0][0] + bv, 0.f), v01 = fmaxf(acc[0][1] + bv, 0.f);
            float v02 = fmaxf(acc[0][2] + bv, 0.f), v03 = fmaxf(acc[0][3] + bv, 0.f);
            float v10 = fmaxf(acc[1][0] + bv, 0.f), v11 = fmaxf(acc[1][1] + bv, 0.f);
            float v12 = fmaxf(acc[1][2] + bv, 0.f), v13 = fmaxf(acc[1][3] + bv, 0.f);
            float o0 = fmaxf(fmaxf(v00, v01), fmaxf(v10, v11));
            float o1 = fmaxf(fmaxf(v02, v03), fmaxf(v12, v13));
            if (FCOUT) {
                float* hp = sh3 + s * FCN + (co * PH + py) * PW + px2 * 2;
                hp[0] = o0; hp[1] = o1;
            } else {
                float2* op = (float2*)&out[(((size_t)(b0 + s) * COUT + co) * PH + py) * PW + px2 * 2];
                *op = make_float2(o0, o1);
            }
            val = o0 + o1;
        }
        if (EPI) {
            #pragma unroll
            for (int off = SEG / 2; off; off >>= 1)
                val += __shfl_xor_sync(0xffffffffu, val, off);
            if ((t & (SEG - 1)) == 0 && item < total)
                atomicAdd(&scm[s * COUT + co], val);
        }
    }

    if (EPI) {
        __syncthreads();
        if (t < SPB) {
            int s = t;
            float dot = 0.f, ssum = 0.f;
            const float inv = 1.f / (float)(PH * PW);
            for (int c = 0; c < COUT; c++) {
                float cm = scm[s * COUT + c] * inv;
                dot  += cm * asum_next[c];
                ssum += cm * cm;
            }
            float v = dot / (sqrtf(25.f * ssum) + EPSF) + 0.5f * tail_next[0] + c_next[0];
            long long f = (long long)floorf(v / R_HASH);
            qh_next[b0 + s] = (int)(((f % 2) + 2) % 2);
        }
    }

    if (FCOUT) {
        __syncthreads();
        int w = t >> 5, lane = t & 31;
        if (w < SPB) {
            const float* hb = sh3 + w * FCN;
            float xv[10];
            #pragma unroll
            for (int j = 0; j < 10; j++) xv[j] = hb[lane + j * 32];
            #pragma unroll
            for (int o = 0; o < 10; o++) {
                float p = 0.f;
                #pragma unroll
                for (int j = 0; j < 10; j++)
                    p += xv[j] * __ldg(Wo + o * 320 + lane + j * 32);
                #pragma unroll
                for (int off = 16; off; off >>= 1)
                    p += __shfl_xor_sync(0xffffffffu, p, off);
                if (lane == 0)
                    fcout[(b0 + w) * 10 + o] = p + __ldg(bo + o);
            }
        }
    }
}

// ---------------------------------------------------------------------------
static inline int smem_bytes(int CIN, int COUT, int SPB, int HP, int WPAD,
                             int fcn, int T)
{
    int fl = SPB * CIN * HP * WPAD + SPB * COUT + SPB * fcn;
    int it = SPB + (SPB + 1) + SPB * COUT + SPB + SPB * CIN + (SPB + 1);
    int cs = CIN * (T / 32);
    return 4 * (fl + it + cs);
}

extern "C" void kernel_launch(void* const* d_in, const int* in_sizes, int n_in,
                              void* d_out, int out_size)
{
    const float* x  = (const float*)d_in[0];
    const float* W1 = (const float*)d_in[1];
    const float* b1 = (const float*)d_in[2];
    const float* a1 = (const float*)d_in[3];
    const float* c1 = (const float*)d_in[4];
    const float* W2 = (const float*)d_in[5];
    const float* b2 = (const float*)d_in[6];
    const float* a2 = (const float*)d_in[7];
    const float* c2 = (const float*)d_in[8];
    const float* W3 = (const float*)d_in[9];
    const float* b3 = (const float*)d_in[10];
    const float* a3 = (const float*)d_in[11];
    const float* c3 = (const float*)d_in[12];
    const float* Wo = (const float*)d_in[13];
    const float* bo = (const float*)d_in[14];
    float* out = (float*)d_out;

    float *h1, *h2, *aux, *w1p, *w2p, *w3p; int *qh, *kh;
    cudaGetSymbolAddress((void**)&h1, g_h1);
    cudaGetSymbolAddress((void**)&h2, g_h2);
    cudaGetSymbolAddress((void**)&qh, g_qh);
    cudaGetSymbolAddress((void**)&kh, g_kh);
    cudaGetSymbolAddress((void**)&aux, g_aux);
    cudaGetSymbolAddress((void**)&w1p, g_w1p);
    cudaGetSymbolAddress((void**)&w2p, g_w2p);
    cudaGetSymbolAddress((void**)&w3p, g_w3p);

    const int sm1 = smem_bytes(3, 16, 1, 36, 36, 0, 256);
    const int sm2 = smem_bytes(16, 20, 1, 20, 24, 0, 160);
    const int sm3 = smem_bytes(20, 20, 2, 12, 12, 320, 160);

    cudaFuncSetAttribute(
        (const void*)conv_fused<3, 16, 32, 32, 36, 1, 256, 4, true, true, false, true>,
        cudaFuncAttributeMaxDynamicSharedMemorySize, sm1);
    cudaFuncSetAttribute(
        (const void*)conv_fused<16, 20, 16, 16, 24, 1, 160, 6, true, false, false, false>,
        cudaFuncAttributeMaxDynamicSharedMemorySize, sm2);
    cudaFuncSetAttribute(
        (const void*)conv_fused<20, 20, 8, 8, 12, 2, 160, 6, false, false, true, false>,
        cudaFuncAttributeMaxDynamicSharedMemorySize, sm3);

    kh_all<<<8, 256>>>(W1, a1, c1, W2, a2, c2, W3, a3, c3);

    // layer 1: computes its own query hash (QHIN) and emits qh2 (EPI)
    conv_fused<3, 16, 32, 32, 36, 1, 256, 4, true, true, false, true><<<BATCH, 256, sm1>>>(
        x, h1, w1p, b1, kh, nullptr, nullptr, nullptr,
        aux + 0, aux + 36, c2, qh + BATCH, nullptr, nullptr, nullptr,
        aux + 38, aux + 41, c1, qh);

    conv_fused<16, 20, 16, 16, 24, 1, 160, 6, true, false, false, false><<<BATCH, 160, sm2>>>(
        h1, h2, w2p, b2, kh + 32, qh + BATCH, kh, qh,
        aux + 16, aux + 37, c3, qh + 2 * BATCH, nullptr, nullptr, nullptr,
        nullptr, nullptr, nullptr, nullptr);

    conv_fused<20, 20, 8, 8, 12, 2, 160, 6, false, false, true, false><<<BATCH / 2, 160, sm3>>>(
        h2, nullptr, w3p, b3, kh + 64, qh + 2 * BATCH, kh + 32, qh + BATCH,
        nullptr, nullptr, nullptr, nullptr, Wo, bo, out,
        nullptr, nullptr, nullptr, nullptr);
}

// round 17
// speedup vs baseline: 1.0323x; 1.0323x over previous
#include <cuda_runtime.h>
#include <math.h>

#define R_HASH 0.2f
#define EPSF   1e-12f
#define BATCH  4096

// scratch (device globals: sanctioned scratch mechanism)
__device__ float g_h1[BATCH * 16 * 16 * 16];
__device__ float g_h2[BATCH * 20 * 8 * 8];
__device__ int   g_qh[3 * BATCH];
__device__ int   g_kh[96];
__device__ float g_aux[48];
__device__ __align__(16) float g_w1p[48 * 28];   // padded weights, stride 28
__device__ __align__(16) float g_w2p[320 * 28];
__device__ __align__(16) float g_w3p[400 * 28];

// ---------------------------------------------------------------------------
// Merged setup kernel:
//   blocks 0-2  : filter hashes (one warp per filter, lane-parallel dots)
//   blocks 3-7  : weight padding + aux sums
//   blocks 8+   : layer-1 query hash, one warp per sample (aux computed
//                 locally with the identical serial order -> bitwise equal)
// ---------------------------------------------------------------------------
__global__ __launch_bounds__(256)
void setup_all(const float* __restrict__ x,
               const float* __restrict__ W1, const float* __restrict__ a1,
               const float* __restrict__ c1,
               const float* __restrict__ W2, const float* __restrict__ a2,
               const float* __restrict__ c2,
               const float* __restrict__ W3, const float* __restrict__ a3,
               const float* __restrict__ c3,
               int* __restrict__ qh_out)
{
    const int blk = blockIdx.x;
    if (blk < 3) {
        const float* W = (blk == 0) ? W1 : (blk == 1) ? W2 : W3;
        const float* a = (blk == 0) ? a1 : (blk == 1) ? a2 : a3;
        const float* c = (blk == 0) ? c1 : (blk == 1) ? c2 : c3;
        const int Cout = (blk == 0) ? 16 : 20;
        const int d    = (blk == 0) ? 75 : (blk == 1) ? 400 : 500;
        int* khp = g_kh + blk * 32;

        __shared__ float norms[32];
        __shared__ float smx;
        int w = threadIdx.x >> 5, lane = threadIdx.x & 31;

        for (int f = w; f < Cout; f += 8) {
            float s = 0.f;
            for (int j = lane; j < d; j += 32) { float v = W[f * d + j]; s += v * v; }
            #pragma unroll
            for (int off = 16; off; off >>= 1)
                s += __shfl_xor_sync(0xffffffffu, s, off);
            if (lane == 0) norms[f] = sqrtf(s);
        }
        __syncthreads();
        if (threadIdx.x < 32) {
            float v = (lane < Cout) ? norms[lane] : 0.f;
            #pragma unroll
            for (int off = 16; off; off >>= 1)
                v = fmaxf(v, __shfl_xor_sync(0xffffffffu, v, off));
            if (lane == 0) smx = v;
        }
        __syncthreads();
        const float scale = 1.f / (smx + EPSF);
        for (int f = w; f < Cout; f += 8) {
            float dot = 0.f, ss = 0.f;
            for (int j = lane; j < d; j += 32) {
                float v = W[f * d + j] * scale;
                dot += v * a[j];
                ss  += v * v;
            }
            #pragma unroll
            for (int off = 16; off; off >>= 1) {
                dot += __shfl_xor_sync(0xffffffffu, dot, off);
                ss  += __shfl_xor_sync(0xffffffffu, ss, off);
            }
            if (lane == 0) {
                float n = sqrtf(ss), p = n;
                #pragma unroll
                for (int m = 0; m < 5; m++) { p = p * p; dot += p * a[d + m]; }
                dot += c[0];
                long long fl = (long long)floorf(dot / R_HASH);
                khp[f] = (int)(((fl % 2) + 2) % 2);
            }
        }
    } else if (blk < 8) {
        const int t = threadIdx.x;
        if (blk == 3) {
            if (t < 16) {
                float s = 0.f; for (int j = 0; j < 25; j++) s += a2[t * 25 + j];
                g_aux[t] = s;
            } else if (t >= 32 && t < 52) {
                int r = t - 32;
                float s = 0.f; for (int j = 0; j < 25; j++) s += a3[r * 25 + j];
                g_aux[16 + r] = s;
            } else if (t >= 64 && t < 67) {
                int r = t - 64;
                float s = 0.f; for (int j = 0; j < 25; j++) s += a1[r * 25 + j];
                g_aux[38 + r] = s;
            } else if (t == 67) {
                float s = 0.f; for (int m = 0; m < 5; m++) s += a2[400 + m];
                g_aux[36] = s;
            } else if (t == 68) {
                float s = 0.f; for (int m = 0; m < 5; m++) s += a3[500 + m];
                g_aux[37] = s;
            } else if (t == 69) {
                float s = 0.f; for (int m = 0; m < 5; m++) s += a1[75 + m];
                g_aux[41] = s;
            }
        }
        const int base = (blk - 3) * 256 + threadIdx.x;
        const int stride = 5 * 256;
        for (int i = base; i < 48 * 28; i += stride) {
            int f = i / 28, k = i % 28;
            g_w1p[i] = (k < 25) ? W1[f * 25 + k] : 0.f;
        }
        for (int i = base; i < 320 * 28; i += stride) {
            int f = i / 28, k = i % 28;
            g_w2p[i] = (k < 25) ? W2[f * 25 + k] : 0.f;
        }
        for (int i = base; i < 400 * 28; i += stride) {
            int f = i / 28, k = i % 28;
            g_w3p[i] = (k < 25) ? W3[f * 25 + k] : 0.f;
        }
    } else {
        // qh1: 8 warps per block, one sample per warp; local aux (same order
        // as g_aux[38..41] computation -> bitwise identical values)
        __shared__ float laux[4];
        int t = threadIdx.x;
        if (t < 3) {
            float s = 0.f; for (int j = 0; j < 25; j++) s += a1[t * 25 + j];
            laux[t] = s;
        } else if (t == 3) {
            float s = 0.f; for (int m = 0; m < 5; m++) s += a1[75 + m];
            laux[3] = s;
        }
        __syncthreads();
        int warp = t >> 5, lane = t & 31;
        int b = (blk - 8) * 8 + warp;
        const float4* xb = (const float4*)(x + (size_t)b * 3072);
        float s[3];
        #pragma unroll
        for (int c = 0; c < 3; c++) {
            float p = 0.f;
            #pragma unroll
            for (int i = lane; i < 256; i += 32) {
                float4 v = xb[c * 256 + i];
                p += (v.x + v.y) + (v.z + v.w);
            }
            #pragma unroll
            for (int off = 16; off; off >>= 1)
                p += __shfl_xor_sync(0xffffffffu, p, off);
            s[c] = p;
        }
        if (lane == 0) {
            float dot = 0.f, ss = 0.f;
            #pragma unroll
            for (int c = 0; c < 3; c++) {
                float cm = s[c] * (1.f / 1024.f);
                dot += cm * laux[c];
                ss  += cm * cm;
            }
            float v = dot / (sqrtf(25.f * ss) + EPSF) + 0.5f * laux[3] + c1[0];
            long long f = (long long)floorf(v / R_HASH);
            qh_out[b] = (int)(((f % 2) + 2) % 2);
        }
    }
}

// ---------------------------------------------------------------------------
// Fused conv5x5(pad2)+bias+relu+mask+maxpool2 (R15 structure).
// Staging: zero-fill tile (float4 STS), then interior rows via float4 LDG.
// NOPREV=true: n_ci==CIN. FCOUT=true: FC epilogue writes final [B,10].
// ---------------------------------------------------------------------------
template <int CIN, int COUT, int H, int W, int WPAD, int SPB, int T, int MINB,
          bool EPI, bool NOPREV, bool FCOUT>
__global__ __launch_bounds__(T, MINB)
void conv_fused(const float* __restrict__ in, float* __restrict__ out,
                const float* __restrict__ wpad, const float* __restrict__ bias,
                const int* __restrict__ kh, const int* __restrict__ qh,
                const int* __restrict__ kh_prev, const int* __restrict__ qh_prev,
                const float* __restrict__ asum_next,
                const float* __restrict__ tail_next,
                const float* __restrict__ c_next, int* __restrict__ qh_next,
                const float* __restrict__ Wo, const float* __restrict__ bo,
                float* __restrict__ fcout)
{
    constexpr int HP = H + 4;
    constexpr int PH = H / 2, PW = W / 2, PX2 = PW / 2;
    constexpr int PP = PH * PX2;
    constexpr int SEG = (PP < 32) ? PP : 32;
    constexpr int CHW = HP * WPAD;
    constexpr int WG = W / 4;                 // float4 groups per row
    constexpr int FCN = COUT * PH * PW;       // per-sample flattened size

    extern __shared__ float sm[];
    float* sx  = sm;
    float* scm = sx + SPB * CIN * CHW;
    float* sh3 = scm + SPB * COUT;            // FCOUT: SPB*FCN, else 0
    int* nact  = (int*)(sh3 + (FCOUT ? SPB * FCN : 0));
    int* soff  = nact + SPB;
    int* actco = soff + SPB + 1;
    int* nci   = actco + SPB * COUT;
    int* actci = nci + SPB;
    int* sxoff = actci + SPB * CIN;

    const int b0 = blockIdx.x * SPB;
    const int t  = threadIdx.x;

    if (t < SPB) {
        int s = t, n = 0, qv = qh[b0 + s];
        for (int co = 0; co < COUT; co++)
            if (kh[co] == qv) actco[s * COUT + n++] = co;
        nact[s] = n;
    } else if (t >= 32 && t < 32 + SPB) {
        int s = t - 32, n = 0;
        if (!NOPREV) {
            int qv = qh_prev[b0 + s];
            for (int c = 0; c < CIN; c++)
                if (kh_prev[c] == qv) actci[s * CIN + n++] = c;
        } else {
            for (int c = 0; c < CIN; c++) actci[s * CIN + n++] = c;
        }
        nci[s] = n;
    }
    if (EPI) for (int i = t; i < SPB * COUT; i += T) scm[i] = 0.f;
    if (FCOUT) for (int i = t; i < SPB * FCN; i += T) sh3[i] = 0.f;
    __syncthreads();
    if (t == 0) {
        int o = 0, xo = 0;
        for (int s = 0; s < SPB; s++) {
            soff[s] = o;  o  += nact[s] * PP;
            sxoff[s] = xo; xo += NOPREV ? CIN : nci[s];
        }
        soff[SPB] = o; sxoff[SPB] = xo;
    }
    __syncthreads();

    const int total_ch = sxoff[SPB];
    // zero-fill used portion of tile (float4 STS)
    {
        float4 z = make_float4(0.f, 0.f, 0.f, 0.f);
        float4* sx4 = (float4*)sx;
        const int n4 = total_ch * (CHW / 4);
        for (int i = t; i < n4; i += T) sx4[i] = z;
    }
    __syncthreads();
    // interior rows via float4 LDG + 4 scalar STS
    for (int i = t; i < total_ch * H * WG; i += T) {
        int xg = i % WG; int rest = i / WG;
        int y = rest % H; int ch = rest / H;
        int s = 0;
        #pragma unroll
        for (int ss = 0; ss < SPB - 1; ss++)
            if (ch >= sxoff[ss + 1]) s = ss + 1;
        int c = NOPREV ? (ch - sxoff[s]) : actci[s * CIN + (ch - sxoff[s])];
        float4 v = *(const float4*)(in + ((size_t)(b0 + s) * CIN + c) * (H * W)
                                    + y * W + 4 * xg);
        float* dst = sx + ch * CHW + (y + 2) * WPAD + 4 * xg + 2;
        dst[0] = v.x; dst[1] = v.y; dst[2] = v.z; dst[3] = v.w;
    }
    __syncthreads();
    const int total = soff[SPB];

    for (int item = t;; item += T) {
        if (!__ballot_sync(0xffffffffu, item < total)) break;
        float val = 0.f;
        int s = 0, co = 0;
        if (item < total) {
            #pragma unroll
            for (int ss = 0; ss < SPB - 1; ss++)
                if (item >= soff[ss + 1]) s = ss + 1;
            int local = item - soff[s];
            co = actco[s * COUT + local / PP];
            int rr = local % PP;
            int py = rr / PX2, px2 = rr % PX2;

            float acc[2][4] = {};
            const float* xb = sx + (size_t)sxoff[s] * CHW + (2 * py) * WPAD + 4 * px2;
            const int n_ci = NOPREV ? CIN : nci[s];
            const int* ci = actci + s * CIN;
            const float* wb_ = wpad + (size_t)co * CIN * 28;

            for (int j = 0; j < n_ci; j++) {
                int c = NOPREV ? j : ci[j];
                const float4* wr = (const float4*)(wb_ + c * 28);
                float4 q0 = __ldg(wr + 0), q1 = __ldg(wr + 1), q2 = __ldg(wr + 2);
                float4 q3 = __ldg(wr + 3), q4 = __ldg(wr + 4), q5 = __ldg(wr + 5);
                float4 q6 = __ldg(wr + 6);
                float w[25] = {q0.x, q0.y, q0.z, q0.w, q1.x, q1.y, q1.z, q1.w,
                               q2.x, q2.y, q2.z, q2.w, q3.x, q3.y, q3.z, q3.w,
                               q4.x, q4.y, q4.z, q4.w, q5.x, q5.y, q5.z, q5.w,
                               q6.x};
                const float* xs = xb + j * CHW;
                #pragma unroll
                for (int rw = 0; rw < 6; rw++) {
                    float4 x0 = *(const float4*)(xs + rw * WPAD);
                    float4 x1 = *(const float4*)(xs + rw * WPAD + 4);
                    float xr[8] = {x0.x, x0.y, x0.z, x0.w, x1.x, x1.y, x1.z, x1.w};
                    if (rw < 5) {
                        #pragma unroll
                        for (int kx = 0; kx < 5; kx++) {
                            float wa = w[rw * 5 + kx];
                            acc[0][0] += xr[kx + 0] * wa;
                            acc[0][1] += xr[kx + 1] * wa;
                            acc[0][2] += xr[kx + 2] * wa;
                            acc[0][3] += xr[kx + 3] * wa;
                        }
                    }
                    if (rw > 0) {
                        #pragma unroll
                        for (int kx = 0; kx < 5; kx++) {
                            float wb = w[(rw - 1) * 5 + kx];
                            acc[1][0] += xr[kx + 0] * wb;
                            acc[1][1] += xr[kx + 1] * wb;
                            acc[1][2] += xr[kx + 2] * wb;
                            acc[1][3] += xr[kx + 3] * wb;
                        }
                    }
                }
            }
            float bv = __ldg(bias + co);
            float v00 = fmaxf(acc[0][0] + bv, 0.f), v01 = fmaxf(acc[0][1] + bv, 0.f);
            float v02 = fmaxf(acc[0][2] + bv, 0.f), v03 = fmaxf(acc[0][3] + bv, 0.f);
            float v10 = fmaxf(acc[1][0] + bv, 0.f), v11 = fmaxf(acc[1][1] + bv, 0.f);
            float v12 = fmaxf(acc[1][2] + bv, 0.f), v13 = fmaxf(acc[1][3] + bv, 0.f);
            float o0 = fmaxf(fmaxf(v00, v01), fmaxf(v10, v11));
            float o1 = fmaxf(fmaxf(v02, v03), fmaxf(v12, v13));
            if (FCOUT) {
                float* hp = sh3 + s * FCN + (co * PH + py) * PW + px2 * 2;
                hp[0] = o0; hp[1] = o1;
            } else {
                float2* op = (float2*)&out[(((size_t)(b0 + s) * COUT + co) * PH + py) * PW + px2 * 2];
                *op = make_float2(o0, o1);
            }
            val = o0 + o1;
        }
        if (EPI) {
            #pragma unroll
            for (int off = SEG / 2; off; off >>= 1)
                val += __shfl_xor_sync(0xffffffffu, val, off);
            if ((t & (SEG - 1)) == 0 && item < total)
                atomicAdd(&scm[s * COUT + co], val);
        }
    }

    if (EPI) {
        __syncthreads();
        if (t < SPB) {
            int s = t;
            float dot = 0.f, ssum = 0.f;
            const float inv = 1.f / (float)(PH * PW);
            for (int c = 0; c < COUT; c++) {
                float cm = scm[s * COUT + c] * inv;
                dot  += cm * asum_next[c];
                ssum += cm * cm;
            }
            float v = dot / (sqrtf(25.f * ssum) + EPSF) + 0.5f * tail_next[0] + c_next[0];
            long long f = (long long)floorf(v / R_HASH);
            qh_next[b0 + s] = (int)(((f % 2) + 2) % 2);
        }
    }

    if (FCOUT) {
        __syncthreads();
        int w = t >> 5, lane = t & 31;
        if (w < SPB) {
            const float* hb = sh3 + w * FCN;
            float xv[10];
            #pragma unroll
            for (int j = 0; j < 10; j++) xv[j] = hb[lane + j * 32];
            #pragma unroll
            for (int o = 0; o < 10; o++) {
                float p = 0.f;
                #pragma unroll
                for (int j = 0; j < 10; j++)
                    p += xv[j] * __ldg(Wo + o * 320 + lane + j * 32);
                #pragma unroll
                for (int off = 16; off; off >>= 1)
                    p += __shfl_xor_sync(0xffffffffu, p, off);
                if (lane == 0)
                    fcout[(b0 + w) * 10 + o] = p + __ldg(bo + o);
            }
        }
    }
}

// ---------------------------------------------------------------------------
static inline int smem_bytes(int CIN, int COUT, int SPB, int HP, int WPAD, int fcn)
{
    int fl = SPB * CIN * HP * WPAD + SPB * COUT + SPB * fcn;
    int it = SPB + (SPB + 1) + SPB * COUT + SPB + SPB * CIN + (SPB + 1);
    return 4 * (fl + it);
}

extern "C" void kernel_launch(void* const* d_in, const int* in_sizes, int n_in,
                              void* d_out, int out_size)
{
    const float* x  = (const float*)d_in[0];
    const float* W1 = (const float*)d_in[1];
    const float* b1 = (const float*)d_in[2];
    const float* a1 = (const float*)d_in[3];
    const float* c1 = (const float*)d_in[4];
    const float* W2 = (const float*)d_in[5];
    const float* b2 = (const float*)d_in[6];
    const float* a2 = (const float*)d_in[7];
    const float* c2 = (const float*)d_in[8];
    const float* W3 = (const float*)d_in[9];
    const float* b3 = (const float*)d_in[10];
    const float* a3 = (const float*)d_in[11];
    const float* c3 = (const float*)d_in[12];
    const float* Wo = (const float*)d_in[13];
    const float* bo = (const float*)d_in[14];
    float* out = (float*)d_out;

    float *h1, *h2, *aux, *w1p, *w2p, *w3p; int *qh, *kh;
    cudaGetSymbolAddress((void**)&h1, g_h1);
    cudaGetSymbolAddress((void**)&h2, g_h2);
    cudaGetSymbolAddress((void**)&qh, g_qh);
    cudaGetSymbolAddress((void**)&kh, g_kh);
    cudaGetSymbolAddress((void**)&aux, g_aux);
    cudaGetSymbolAddress((void**)&w1p, g_w1p);
    cudaGetSymbolAddress((void**)&w2p, g_w2p);
    cudaGetSymbolAddress((void**)&w3p, g_w3p);

    const int sm1 = smem_bytes(3, 16, 1, 36, 36, 0);
    const int sm2 = smem_bytes(16, 20, 1, 20, 24, 0);
    const int sm3 = smem_bytes(20, 20, 2, 12, 12, 320);

    cudaFuncSetAttribute(
        (const void*)conv_fused<3, 16, 32, 32, 36, 1, 128, 8, true, true, false>,
        cudaFuncAttributeMaxDynamicSharedMemorySize, sm1);
    cudaFuncSetAttribute(
        (const void*)conv_fused<16, 20, 16, 16, 24, 1, 160, 6, true, false, false>,
        cudaFuncAttributeMaxDynamicSharedMemorySize, sm2);
    cudaFuncSetAttribute(
        (const void*)conv_fused<20, 20, 8, 8, 12, 2, 160, 6, false, false, true>,
        cudaFuncAttributeMaxDynamicSharedMemorySize, sm3);

    // merged setup: filter hashes + weight padding + layer-1 query hashes
    setup_all<<<8 + BATCH / 8, 256>>>(x, W1, a1, c1, W2, a2, c2, W3, a3, c3, qh);

    conv_fused<3, 16, 32, 32, 36, 1, 128, 8, true, true, false><<<BATCH, 128, sm1>>>(
        x, h1, w1p, b1, kh, qh, nullptr, nullptr,
        aux + 0, aux + 36, c2, qh + BATCH, nullptr, nullptr, nullptr);

    conv_fused<16, 20, 16, 16, 24, 1, 160, 6, true, false, false><<<BATCH, 160, sm2>>>(
        h1, h2, w2p, b2, kh + 32, qh + BATCH, kh, qh,
        aux + 16, aux + 37, c3, qh + 2 * BATCH, nullptr, nullptr, nullptr);

    conv_fused<20, 20, 8, 8, 12, 2, 160, 6, false, false, true><<<BATCH / 2, 160, sm3>>>(
        h2, nullptr, w3p, b3, kh + 64, qh + 2 * BATCH, kh + 32, qh + BATCH,
        nullptr, nullptr, nullptr, nullptr, Wo, bo, out);
}